// round 15
// baseline (speedup 1.0000x reference)
#include <cuda_runtime.h>
#include <cuda_fp16.h>
#include <cstdint>

// ---------------------------------------------------------------------------
// Problem constants
// ---------------------------------------------------------------------------
constexpr int R_ = 64, C_ = 512, H_ = 12, D_ = 64, E_ = 768;
constexpr int M_TOK = R_ * C_;   // 32768
constexpr int RD    = R_ * D_;   // 4096
constexpr int HRD   = H_ * RD;   // 49152
constexpr long OUT_OFF_P = (long)M_TOK * E_;
constexpr long OUT_OFF_L = OUT_OFF_P + (long)H_ * C_ * C_;
constexpr float SCALING = 0.015625f;  // D^-0.5 / sqrt(R)
constexpr int KSPLIT = 4;
constexpr int KPART  = RD / KSPLIT;   // 1024

// ---------------------------------------------------------------------------
// Scratch
// ---------------------------------------------------------------------------
__device__ __half g_xh [(size_t)M_TOK * E_];
__device__ __half g_Wh [4 * (size_t)E_ * E_];
__device__ __half g_Q  [(size_t)C_ * HRD];          // [i][h][r][d]
__device__ __half g_K  [(size_t)C_ * HRD];          // [i][h][r][d]
__device__ __half g_Vt [(size_t)H_ * RD * C_];      // [h][r*D+d][i]
__device__ float  g_Sp [(size_t)H_ * KSPLIT * C_ * C_];
__device__ __half g_P  [(size_t)H_ * C_ * C_];
__device__ __half g_ctx[(size_t)M_TOK * E_];

// ---------------------------------------------------------------------------
// Side stream + events (host-side resources only, created at load time).
// Used to overlap the two independent f2h conversion passes.
// ---------------------------------------------------------------------------
struct AuxStreams {
    cudaStream_t sB;
    cudaEvent_t  evFork, evJoin;
    AuxStreams() {
        cudaStreamCreateWithFlags(&sB, cudaStreamNonBlocking);
        cudaEventCreateWithFlags(&evFork, cudaEventDisableTiming);
        cudaEventCreateWithFlags(&evJoin, cudaEventDisableTiming);
    }
};
static AuxStreams g_aux;

// ---------------------------------------------------------------------------
// Helpers
// ---------------------------------------------------------------------------
__device__ __forceinline__ uint32_t smem_u32(const void* p) {
    uint32_t a;
    asm("{ .reg .u64 t; cvta.to.shared.u64 t, %1; cvt.u32.u64 %0, t; }"
        : "=r"(a) : "l"(p));
    return a;
}
__device__ __forceinline__ void cpa16(uint32_t dst, const void* src) {
    asm volatile("cp.async.cg.shared.global [%0], [%1], 16;"
                 :: "r"(dst), "l"(src) : "memory");
}
__device__ __forceinline__ void ldsm4(uint32_t& r0, uint32_t& r1,
                                      uint32_t& r2, uint32_t& r3, uint32_t addr) {
    asm volatile("ldmatrix.sync.aligned.m8n8.x4.shared.b16 {%0,%1,%2,%3}, [%4];"
                 : "=r"(r0), "=r"(r1), "=r"(r2), "=r"(r3) : "r"(addr));
}

__global__ void __launch_bounds__(256)
f2h_kernel(const float* __restrict__ in, __half* __restrict__ out, int n4) {
    int i = blockIdx.x * blockDim.x + threadIdx.x;
    if (i < n4) {
        float4 v = ((const float4*)in)[i];
        __half2* o = (__half2*)(out + (size_t)i * 4);
        o[0] = __floats2half2_rn(v.x, v.y);
        o[1] = __floats2half2_rn(v.z, v.w);
    }
}

__global__ void __launch_bounds__(256)
f2h_w_kernel(const float* __restrict__ w0, const float* __restrict__ w1,
             const float* __restrict__ w2, const float* __restrict__ w3,
             __half* __restrict__ out, int n4) {
    int i = blockIdx.x * blockDim.x + threadIdx.x;
    if (i >= n4) return;
    const float* src = (blockIdx.y == 0) ? w0 : (blockIdx.y == 1) ? w1
                      : (blockIdx.y == 2) ? w2 : w3;
    float4 v = ((const float4*)src)[i];
    __half2* o = (__half2*)(out + (size_t)blockIdx.y * E_ * E_ + (size_t)i * 4);
    o[0] = __floats2half2_rn(v.x, v.y);
    o[1] = __floats2half2_rn(v.z, v.w);
}

// ---------------------------------------------------------------------------
// fp16 mma.sync GEMM, fp32 accumulate. Block 128x64x64, 8 warps (4m x 2n),
// warp tile 32x32. 2-stage cp.async pipeline, BK=64. 3 CTAs/SM (24 warps).
// Pipeline ordering: wait -> barrier -> issue next load -> compute. (verified)
// ---------------------------------------------------------------------------
constexpr int BM = 128, BN = 64, BK = 64;
constexpr int STAGES = 2;
constexpr int AS_STRIDE = 72;                     // halves per row (144 B)
constexpr int BS_STRIDE = 72;
constexpr int AS_HALVES = BM * AS_STRIDE;         // 9216
constexpr int BS_HALVES = BN * BS_STRIDE;         // 4608
constexpr int STAGE_HALVES = AS_HALVES + BS_HALVES;   // 13824 (27648 B)
constexpr int SMEM_BYTES = STAGES * STAGE_HALVES * 2; // 55296

enum { EPI_PROJ = 0, EPI_LOGITS = 2, EPI_CTX = 3, EPI_OPROJ = 4 };

template <int EPI>
__global__ void __launch_bounds__(256, 3)
mm_kernel(const __half* __restrict__ A, const __half* __restrict__ Bw,
          const float* __restrict__ biasQ, const float* __restrict__ biasK,
          const float* __restrict__ biasV,
          __half* __restrict__ dQ, __half* __restrict__ dK, __half* __restrict__ dVt,
          float* __restrict__ CoutF, __half* __restrict__ CoutH,
          int lda, int ldb, int K)
{
    extern __shared__ __half sm[];
    const int tid = threadIdx.x;
    const int wid = tid >> 5, lane = tid & 31;
    const int m0 = blockIdx.y * BM;
    const int n0 = blockIdx.x * BN;
    const int z  = blockIdx.z;

    const __half* B = Bw;
    if (EPI == EPI_PROJ)   { B  = Bw + (size_t)z * E_ * E_; }
    if (EPI == EPI_LOGITS) {
        const int head = z >> 2, kh = z & 3;     // z = head*KSPLIT + kpart
        A += (size_t)head * RD + (size_t)kh * KPART;
        B  = Bw + (size_t)head * RD + (size_t)kh * KPART;
    }
    if (EPI == EPI_CTX)    { A += (size_t)z * C_ * C_; B = Bw + (size_t)z * RD * C_; }

    const uint32_t smb = smem_u32(sm);

    const int warp_m = wid >> 1;          // 0..3 -> 32-row slices
    const int warp_n = wid & 1;           // 0..1 -> 32-col slices
    const int mb_base = warp_m * 32;
    const int nb_base = warp_n * 32;
    const int r4 = lane >> 2, c4 = lane & 3;

    const uint32_t a_off =
        (uint32_t)(((mb_base + (lane & 15)) * AS_STRIDE + ((lane >> 4) * 8)) * 2);
    const uint32_t b_off =
        (uint32_t)(((nb_base + (lane & 7) + ((lane & 16) >> 1)) * BS_STRIDE +
                    (((lane >> 3) & 1) * 8)) * 2);

    float acc[2][4][4];
#pragma unroll
    for (int a = 0; a < 2; a++)
#pragma unroll
        for (int b = 0; b < 4; b++)
#pragma unroll
            for (int c = 0; c < 4; c++) acc[a][b][c] = 0.f;

    const int NC = K / BK;

    auto load_stage = [&](int c, int s) {
        const __half* Ab = A + (size_t)m0 * lda + c * BK;
        const __half* Bb = B + (size_t)n0 * ldb + c * BK;
        const uint32_t asb = smb + (uint32_t)(s * STAGE_HALVES) * 2u;
        const uint32_t bsb = asb + AS_HALVES * 2u;
#pragma unroll
        for (int i = 0; i < 4; i++) {          // A: 128 rows x 8 f8 = 1024 cp
            int q = i * 256 + tid;
            int row = q >> 3, kq = q & 7;
            cpa16(asb + (uint32_t)(row * AS_STRIDE + kq * 8) * 2u,
                  Ab + (size_t)row * lda + kq * 8);
        }
#pragma unroll
        for (int i = 0; i < 2; i++) {          // B: 64 rows x 8 f8 = 512 cp
            int q = i * 256 + tid;
            int row = q >> 3, kq = q & 7;
            cpa16(bsb + (uint32_t)(row * BS_STRIDE + kq * 8) * 2u,
                  Bb + (size_t)row * ldb + kq * 8);
        }
        asm volatile("cp.async.commit_group;" ::: "memory");
    };

    load_stage(0, 0);

    int sidx = 0;
    for (int c = 0; c < NC; c++) {
        // wait for ALL outstanding loads (including load(c)), then barrier:
        // publishes load(c) to every warp AND guarantees no warp still reads
        // buffer sidx^1 (iteration c-1) before we overwrite it below.
        asm volatile("cp.async.wait_group 0;" ::: "memory");
        __syncthreads();

        if (c + 1 < NC) load_stage(c + 1, sidx ^ 1);   // overlaps compute below

        const uint32_t abase = smb + (uint32_t)(sidx * STAGE_HALVES) * 2u + a_off;
        const uint32_t bbase = smb + (uint32_t)(sidx * STAGE_HALVES + AS_HALVES) * 2u + b_off;

#pragma unroll
        for (int s = 0; s < 4; s++) {          // 4 substeps of k16
            const int ks = s * 16;
            uint32_t afr[2][4], bfr[4][2];
#pragma unroll
            for (int mb = 0; mb < 2; mb++)
                ldsm4(afr[mb][0], afr[mb][1], afr[mb][2], afr[mb][3],
                      abase + (uint32_t)((mb * 16 * AS_STRIDE + ks) * 2));
#pragma unroll
            for (int p = 0; p < 2; p++)
                ldsm4(bfr[2*p][0], bfr[2*p][1], bfr[2*p+1][0], bfr[2*p+1][1],
                      bbase + (uint32_t)((p * 16 * BS_STRIDE + ks) * 2));
#pragma unroll
            for (int mb = 0; mb < 2; mb++)
#pragma unroll
                for (int nb = 0; nb < 4; nb++) {
                    asm volatile(
                        "mma.sync.aligned.m16n8k16.row.col.f32.f16.f16.f32 "
                        "{%0,%1,%2,%3}, {%4,%5,%6,%7}, {%8,%9}, {%0,%1,%2,%3};"
                        : "+f"(acc[mb][nb][0]), "+f"(acc[mb][nb][1]),
                          "+f"(acc[mb][nb][2]), "+f"(acc[mb][nb][3])
                        : "r"(afr[mb][0]), "r"(afr[mb][1]),
                          "r"(afr[mb][2]), "r"(afr[mb][3]),
                          "r"(bfr[nb][0]), "r"(bfr[nb][1]));
                }
        }
        sidx ^= 1;
    }

    // ---- epilogue
#pragma unroll
    for (int mb = 0; mb < 2; mb++) {
#pragma unroll
        for (int half_ = 0; half_ < 2; half_++) {
            const int m = m0 + mb_base + mb * 16 + r4 + half_ * 8;
#pragma unroll
            for (int nb = 0; nb < 4; nb++) {
                const int n = n0 + nb_base + nb * 8 + c4 * 2;
                float v0 = acc[mb][nb][half_ * 2 + 0];
                float v1 = acc[mb][nb][half_ * 2 + 1];

                if (EPI == EPI_PROJ) {
                    const int r = m >> 9, ic = m & 511;
                    const int h = n >> 6, d = n & 63;
                    if (z == 0) {
                        v0 = (v0 + biasQ[n])     * SCALING;
                        v1 = (v1 + biasQ[n + 1]) * SCALING;
                        *(__half2*)(dQ + (((size_t)ic * H_ + h) * R_ + r) * D_ + d) =
                            __floats2half2_rn(v0, v1);
                    } else if (z == 1) {
                        v0 += biasK[n]; v1 += biasK[n + 1];
                        *(__half2*)(dK + (((size_t)ic * H_ + h) * R_ + r) * D_ + d) =
                            __floats2half2_rn(v0, v1);
                    } else {
                        v0 += biasV[n]; v1 += biasV[n + 1];
                        __half* dst = dVt + ((size_t)h * RD + r * D_ + d) * C_ + ic;
                        dst[0]  = __float2half_rn(v0);
                        dst[C_] = __float2half_rn(v1);
                    }
                } else if (EPI == EPI_LOGITS) {
                    float2* dst = (float2*)(CoutF + ((size_t)z * C_ + m) * C_ + n);
                    *dst = make_float2(v0, v1);
                } else if (EPI == EPI_CTX) {
                    const int r = n >> 6, d = n & 63;
                    *(__half2*)(CoutH + ((size_t)(r * C_) + m) * E_ + z * D_ + d) =
                        __floats2half2_rn(v0, v1);
                } else { // EPI_OPROJ
                    float2* dst = (float2*)(CoutF + (size_t)m * E_ + n);
                    *dst = make_float2(v0 + biasQ[n], v1 + biasQ[n + 1]);
                }
            }
        }
    }
}

// ---------------------------------------------------------------------------
// Masked softmax; sums KSPLIT partials. fp32 to d_out, fp16 to P.
// Block 0 also copies the l passthrough (fused, saves a launch).
// ---------------------------------------------------------------------------
__global__ void __launch_bounds__(512)
softmax_kernel(const float* __restrict__ Sp, __half* __restrict__ P,
               float* __restrict__ Pout,
               const float* __restrict__ l, float* __restrict__ lOut)
{
    const int row = blockIdx.x;
    const int h   = row >> 9;
    const int i   = row & (C_ - 1);
    const int j   = threadIdx.x;
    const int lane = j & 31, warp = j >> 5;
    __shared__ float red[16];

    if (row == 0 && j < H_) lOut[j] = l[j];

    const float* base = Sp + (((size_t)h * KSPLIT) * C_ + i) * C_ + j;
    float x = base[0];
#pragma unroll
    for (int kh = 1; kh < KSPLIT; kh++)
        x += base[(size_t)kh * C_ * C_];
    if (j == i) x = -1e9f;

    float m = x;
#pragma unroll
    for (int o = 16; o > 0; o >>= 1) m = fmaxf(m, __shfl_xor_sync(~0u, m, o));
    if (lane == 0) red[warp] = m;
    __syncthreads();
    if (j < 16) {
        float t = red[j];
#pragma unroll
        for (int o = 8; o > 0; o >>= 1) t = fmaxf(t, __shfl_xor_sync(0xffffu, t, o));
        if (j == 0) red[0] = t;
    }
    __syncthreads();
    const float mx = red[0];
    __syncthreads();

    float e = __expf(x - mx);
    float sacc = e;
#pragma unroll
    for (int o = 16; o > 0; o >>= 1) sacc += __shfl_xor_sync(~0u, sacc, o);
    if (lane == 0) red[warp] = sacc;
    __syncthreads();
    if (j < 16) {
        float t = red[j];
#pragma unroll
        for (int o = 8; o > 0; o >>= 1) t += __shfl_xor_sync(0xffffu, t, o);
        if (j == 0) red[0] = t;
    }
    __syncthreads();
    const float inv = 1.0f / red[0];

    const float p = e * inv;
    const size_t idx = (size_t)row * C_ + j;
    P[idx]    = __float2half_rn(p);
    Pout[idx] = p;
}

// ---------------------------------------------------------------------------
// Launch
// ---------------------------------------------------------------------------
extern "C" void kernel_launch(void* const* d_in, const int* in_sizes, int n_in,
                              void* d_out, int out_size)
{
    const float* x  = (const float*)d_in[0];
    const float* Wq = (const float*)d_in[2];
    const float* bq = (const float*)d_in[3];
    const float* Wk = (const float*)d_in[4];
    const float* bk = (const float*)d_in[5];
    const float* Wv = (const float*)d_in[6];
    const float* bv = (const float*)d_in[7];
    const float* Wo = (const float*)d_in[8];
    const float* bo = (const float*)d_in[9];
    const float* l  = (const float*)d_in[10];
    float* out = (float*)d_out;

    __half *pXh, *pWh, *pQ, *pK, *pVt, *pP, *pCtx;
    float *pSp;
    cudaGetSymbolAddress((void**)&pXh,  g_xh);
    cudaGetSymbolAddress((void**)&pWh,  g_Wh);
    cudaGetSymbolAddress((void**)&pQ,   g_Q);
    cudaGetSymbolAddress((void**)&pK,   g_K);
    cudaGetSymbolAddress((void**)&pVt,  g_Vt);
    cudaGetSymbolAddress((void**)&pSp,  g_Sp);
    cudaGetSymbolAddress((void**)&pP,   g_P);
    cudaGetSymbolAddress((void**)&pCtx, g_ctx);

    cudaFuncSetAttribute(mm_kernel<EPI_PROJ>,   cudaFuncAttributeMaxDynamicSharedMemorySize, SMEM_BYTES);
    cudaFuncSetAttribute(mm_kernel<EPI_LOGITS>, cudaFuncAttributeMaxDynamicSharedMemorySize, SMEM_BYTES);
    cudaFuncSetAttribute(mm_kernel<EPI_CTX>,    cudaFuncAttributeMaxDynamicSharedMemorySize, SMEM_BYTES);
    cudaFuncSetAttribute(mm_kernel<EPI_OPROJ>,  cudaFuncAttributeMaxDynamicSharedMemorySize, SMEM_BYTES);

    const size_t WSZ = (size_t)E_ * E_;

    // 0) fp16 conversion: x on legacy stream, the 4 W's concurrently on the
    //    side stream (independent inputs; join before the projections).
    {
        cudaEventRecord(g_aux.evFork, 0);
        cudaStreamWaitEvent(g_aux.sB, g_aux.evFork, 0);
        int n4w = (int)(WSZ / 4);
        dim3 gW((n4w + 255) / 256, 4);
        f2h_w_kernel<<<gW, 256, 0, g_aux.sB>>>(Wq, Wk, Wv, Wo, pWh, n4w);
        cudaEventRecord(g_aux.evJoin, g_aux.sB);

        int n4x = (int)((size_t)M_TOK * E_ / 4);
        f2h_kernel<<<(n4x + 255) / 256, 256>>>(x, pXh, n4x);

        cudaStreamWaitEvent(0, g_aux.evJoin, 0);
    }

    const dim3 gProj (E_ / BN, M_TOK / BM, 3);          // 12 x 256 x 3
    const dim3 gLog  (C_ / BN, C_ / BM, H_ * KSPLIT);   // 8 x 4 x 48
    const dim3 gCtx  (RD / BN, C_ / BM, H_);            // 64 x 4 x 12
    const dim3 gOut  (E_ / BN, M_TOK / BM, 1);          // 12 x 256

    // 1) fused Q/K/V projections
    mm_kernel<EPI_PROJ><<<gProj, 256, SMEM_BYTES>>>(
        pXh, pWh, bq, bk, bv, pQ, pK, pVt, nullptr, nullptr, E_, E_, E_);

    // 2) tied-row logits, split-K x4 (z = head*4 + kpart, K = 1024 each)
    mm_kernel<EPI_LOGITS><<<gLog, 256, SMEM_BYTES>>>(
        pQ, pK, nullptr, nullptr, nullptr, nullptr, nullptr, nullptr,
        pSp, nullptr, HRD, HRD, KPART);

    // 3) masked softmax (+ fused l passthrough)
    softmax_kernel<<<H_ * C_, 512>>>(pSp, pP, out + OUT_OFF_P,
                                     l, out + OUT_OFF_L);

    // 4) context
    mm_kernel<EPI_CTX><<<gCtx, 256, SMEM_BYTES>>>(
        pP, pVt, nullptr, nullptr, nullptr, nullptr, nullptr, nullptr,
        nullptr, pCtx, C_, C_, C_);

    // 5) output projection
    mm_kernel<EPI_OPROJ><<<gOut, 256, SMEM_BYTES>>>(
        pCtx, pWh + 3 * WSZ, bo, nullptr, nullptr, nullptr, nullptr, nullptr,
        out, nullptr, E_, E_, E_);
}

// round 16
// speedup vs baseline: 1.0019x; 1.0019x over previous
#include <cuda_runtime.h>
#include <cuda_fp16.h>
#include <cstdint>

// ---------------------------------------------------------------------------
// Problem constants
// ---------------------------------------------------------------------------
constexpr int R_ = 64, C_ = 512, H_ = 12, D_ = 64, E_ = 768;
constexpr int M_TOK = R_ * C_;   // 32768
constexpr int RD    = R_ * D_;   // 4096
constexpr int HRD   = H_ * RD;   // 49152
constexpr long OUT_OFF_P = (long)M_TOK * E_;
constexpr long OUT_OFF_L = OUT_OFF_P + (long)H_ * C_ * C_;
constexpr float SCALING = 0.015625f;  // D^-0.5 / sqrt(R)
constexpr int KSPLIT = 4;
constexpr int KPART  = RD / KSPLIT;   // 1024

// ---------------------------------------------------------------------------
// Scratch
// ---------------------------------------------------------------------------
__device__ __half g_xh [(size_t)M_TOK * E_];
__device__ __half g_Wh [4 * (size_t)E_ * E_];
__device__ __half g_Q  [(size_t)C_ * HRD];          // [i][h][r][d]
__device__ __half g_K  [(size_t)C_ * HRD];          // [i][h][r][d]
__device__ __half g_Vt [(size_t)H_ * RD * C_];      // [h][r*D+d][i]
__device__ __half g_Sp [(size_t)H_ * KSPLIT * C_ * C_];  // fp16 logit partials
__device__ __half g_P  [(size_t)H_ * C_ * C_];
__device__ __half g_ctx[(size_t)M_TOK * E_];

// ---------------------------------------------------------------------------
// Side stream + events (host-side resources only, created at load time).
// ---------------------------------------------------------------------------
struct AuxStreams {
    cudaStream_t sB;
    cudaEvent_t  evFork, evJoin;
    AuxStreams() {
        cudaStreamCreateWithFlags(&sB, cudaStreamNonBlocking);
        cudaEventCreateWithFlags(&evFork, cudaEventDisableTiming);
        cudaEventCreateWithFlags(&evJoin, cudaEventDisableTiming);
    }
};
static AuxStreams g_aux;

// ---------------------------------------------------------------------------
// Helpers
// ---------------------------------------------------------------------------
__device__ __forceinline__ uint32_t smem_u32(const void* p) {
    uint32_t a;
    asm("{ .reg .u64 t; cvta.to.shared.u64 t, %1; cvt.u32.u64 %0, t; }"
        : "=r"(a) : "l"(p));
    return a;
}
__device__ __forceinline__ void cpa16(uint32_t dst, const void* src) {
    asm volatile("cp.async.cg.shared.global [%0], [%1], 16;"
                 :: "r"(dst), "l"(src) : "memory");
}
__device__ __forceinline__ void ldsm4(uint32_t& r0, uint32_t& r1,
                                      uint32_t& r2, uint32_t& r3, uint32_t addr) {
    asm volatile("ldmatrix.sync.aligned.m8n8.x4.shared.b16 {%0,%1,%2,%3}, [%4];"
                 : "=r"(r0), "=r"(r1), "=r"(r2), "=r"(r3) : "r"(addr));
}

__global__ void __launch_bounds__(256)
f2h_kernel(const float* __restrict__ in, __half* __restrict__ out, int n4) {
    int i = blockIdx.x * blockDim.x + threadIdx.x;
    if (i < n4) {
        float4 v = ((const float4*)in)[i];
        __half2* o = (__half2*)(out + (size_t)i * 4);
        o[0] = __floats2half2_rn(v.x, v.y);
        o[1] = __floats2half2_rn(v.z, v.w);
    }
}

__global__ void __launch_bounds__(256)
f2h_w_kernel(const float* __restrict__ w0, const float* __restrict__ w1,
             const float* __restrict__ w2, const float* __restrict__ w3,
             __half* __restrict__ out, int n4) {
    int i = blockIdx.x * blockDim.x + threadIdx.x;
    if (i >= n4) return;
    const float* src = (blockIdx.y == 0) ? w0 : (blockIdx.y == 1) ? w1
                      : (blockIdx.y == 2) ? w2 : w3;
    float4 v = ((const float4*)src)[i];
    __half2* o = (__half2*)(out + (size_t)blockIdx.y * E_ * E_ + (size_t)i * 4);
    o[0] = __floats2half2_rn(v.x, v.y);
    o[1] = __floats2half2_rn(v.z, v.w);
}

// ---------------------------------------------------------------------------
// fp16 mma.sync GEMM, fp32 accumulate. Block 128x64x64, 8 warps (4m x 2n),
// warp tile 32x32. 2-stage cp.async pipeline, BK=64. 3 CTAs/SM (24 warps).
// Pipeline ordering: wait -> barrier -> issue next load -> compute. (verified)
// ---------------------------------------------------------------------------
constexpr int BM = 128, BN = 64, BK = 64;
constexpr int STAGES = 2;
constexpr int AS_STRIDE = 72;                     // halves per row (144 B)
constexpr int BS_STRIDE = 72;
constexpr int AS_HALVES = BM * AS_STRIDE;         // 9216
constexpr int BS_HALVES = BN * BS_STRIDE;         // 4608
constexpr int STAGE_HALVES = AS_HALVES + BS_HALVES;   // 13824 (27648 B)
constexpr int SMEM_BYTES = STAGES * STAGE_HALVES * 2; // 55296

enum { EPI_PROJ = 0, EPI_LOGITS = 2, EPI_CTX = 3, EPI_OPROJ = 4 };

template <int EPI>
__global__ void __launch_bounds__(256, 3)
mm_kernel(const __half* __restrict__ A, const __half* __restrict__ Bw,
          const float* __restrict__ biasQ, const float* __restrict__ biasK,
          const float* __restrict__ biasV,
          __half* __restrict__ dQ, __half* __restrict__ dK, __half* __restrict__ dVt,
          float* __restrict__ CoutF, __half* __restrict__ CoutH,
          int lda, int ldb, int K)
{
    extern __shared__ __half sm[];
    const int tid = threadIdx.x;
    const int wid = tid >> 5, lane = tid & 31;
    const int m0 = blockIdx.y * BM;
    const int n0 = blockIdx.x * BN;
    const int z  = blockIdx.z;

    const __half* B = Bw;
    if (EPI == EPI_PROJ)   { B  = Bw + (size_t)z * E_ * E_; }
    if (EPI == EPI_LOGITS) {
        const int head = z >> 2, kh = z & 3;     // z = head*KSPLIT + kpart
        A += (size_t)head * RD + (size_t)kh * KPART;
        B  = Bw + (size_t)head * RD + (size_t)kh * KPART;
    }
    if (EPI == EPI_CTX)    { A += (size_t)z * C_ * C_; B = Bw + (size_t)z * RD * C_; }

    const uint32_t smb = smem_u32(sm);

    const int warp_m = wid >> 1;          // 0..3 -> 32-row slices
    const int warp_n = wid & 1;           // 0..1 -> 32-col slices
    const int mb_base = warp_m * 32;
    const int nb_base = warp_n * 32;
    const int r4 = lane >> 2, c4 = lane & 3;

    const uint32_t a_off =
        (uint32_t)(((mb_base + (lane & 15)) * AS_STRIDE + ((lane >> 4) * 8)) * 2);
    const uint32_t b_off =
        (uint32_t)(((nb_base + (lane & 7) + ((lane & 16) >> 1)) * BS_STRIDE +
                    (((lane >> 3) & 1) * 8)) * 2);

    float acc[2][4][4];
#pragma unroll
    for (int a = 0; a < 2; a++)
#pragma unroll
        for (int b = 0; b < 4; b++)
#pragma unroll
            for (int c = 0; c < 4; c++) acc[a][b][c] = 0.f;

    const int NC = K / BK;

    auto load_stage = [&](int c, int s) {
        const __half* Ab = A + (size_t)m0 * lda + c * BK;
        const __half* Bb = B + (size_t)n0 * ldb + c * BK;
        const uint32_t asb = smb + (uint32_t)(s * STAGE_HALVES) * 2u;
        const uint32_t bsb = asb + AS_HALVES * 2u;
#pragma unroll
        for (int i = 0; i < 4; i++) {          // A: 128 rows x 8 f8 = 1024 cp
            int q = i * 256 + tid;
            int row = q >> 3, kq = q & 7;
            cpa16(asb + (uint32_t)(row * AS_STRIDE + kq * 8) * 2u,
                  Ab + (size_t)row * lda + kq * 8);
        }
#pragma unroll
        for (int i = 0; i < 2; i++) {          // B: 64 rows x 8 f8 = 512 cp
            int q = i * 256 + tid;
            int row = q >> 3, kq = q & 7;
            cpa16(bsb + (uint32_t)(row * BS_STRIDE + kq * 8) * 2u,
                  Bb + (size_t)row * ldb + kq * 8);
        }
        asm volatile("cp.async.commit_group;" ::: "memory");
    };

    load_stage(0, 0);

    int sidx = 0;
    for (int c = 0; c < NC; c++) {
        // wait for ALL outstanding loads (including load(c)), then barrier:
        // publishes load(c) to every warp AND guarantees no warp still reads
        // buffer sidx^1 (iteration c-1) before we overwrite it below.
        asm volatile("cp.async.wait_group 0;" ::: "memory");
        __syncthreads();

        if (c + 1 < NC) load_stage(c + 1, sidx ^ 1);   // overlaps compute below

        const uint32_t abase = smb + (uint32_t)(sidx * STAGE_HALVES) * 2u + a_off;
        const uint32_t bbase = smb + (uint32_t)(sidx * STAGE_HALVES + AS_HALVES) * 2u + b_off;

#pragma unroll
        for (int s = 0; s < 4; s++) {          // 4 substeps of k16
            const int ks = s * 16;
            uint32_t afr[2][4], bfr[4][2];
#pragma unroll
            for (int mb = 0; mb < 2; mb++)
                ldsm4(afr[mb][0], afr[mb][1], afr[mb][2], afr[mb][3],
                      abase + (uint32_t)((mb * 16 * AS_STRIDE + ks) * 2));
#pragma unroll
            for (int p = 0; p < 2; p++)
                ldsm4(bfr[2*p][0], bfr[2*p][1], bfr[2*p+1][0], bfr[2*p+1][1],
                      bbase + (uint32_t)((p * 16 * BS_STRIDE + ks) * 2));
#pragma unroll
            for (int mb = 0; mb < 2; mb++)
#pragma unroll
                for (int nb = 0; nb < 4; nb++) {
                    asm volatile(
                        "mma.sync.aligned.m16n8k16.row.col.f32.f16.f16.f32 "
                        "{%0,%1,%2,%3}, {%4,%5,%6,%7}, {%8,%9}, {%0,%1,%2,%3};"
                        : "+f"(acc[mb][nb][0]), "+f"(acc[mb][nb][1]),
                          "+f"(acc[mb][nb][2]), "+f"(acc[mb][nb][3])
                        : "r"(afr[mb][0]), "r"(afr[mb][1]),
                          "r"(afr[mb][2]), "r"(afr[mb][3]),
                          "r"(bfr[nb][0]), "r"(bfr[nb][1]));
                }
        }
        sidx ^= 1;
    }

    // ---- epilogue
#pragma unroll
    for (int mb = 0; mb < 2; mb++) {
#pragma unroll
        for (int half_ = 0; half_ < 2; half_++) {
            const int m = m0 + mb_base + mb * 16 + r4 + half_ * 8;
#pragma unroll
            for (int nb = 0; nb < 4; nb++) {
                const int n = n0 + nb_base + nb * 8 + c4 * 2;
                float v0 = acc[mb][nb][half_ * 2 + 0];
                float v1 = acc[mb][nb][half_ * 2 + 1];

                if (EPI == EPI_PROJ) {
                    const int r = m >> 9, ic = m & 511;
                    const int h = n >> 6, d = n & 63;
                    if (z == 0) {
                        v0 = (v0 + biasQ[n])     * SCALING;
                        v1 = (v1 + biasQ[n + 1]) * SCALING;
                        *(__half2*)(dQ + (((size_t)ic * H_ + h) * R_ + r) * D_ + d) =
                            __floats2half2_rn(v0, v1);
                    } else if (z == 1) {
                        v0 += biasK[n]; v1 += biasK[n + 1];
                        *(__half2*)(dK + (((size_t)ic * H_ + h) * R_ + r) * D_ + d) =
                            __floats2half2_rn(v0, v1);
                    } else {
                        v0 += biasV[n]; v1 += biasV[n + 1];
                        __half* dst = dVt + ((size_t)h * RD + r * D_ + d) * C_ + ic;
                        dst[0]  = __float2half_rn(v0);
                        dst[C_] = __float2half_rn(v1);
                    }
                } else if (EPI == EPI_LOGITS) {
                    // fp16 partials halve softmax-side traffic
                    *(__half2*)(CoutH + ((size_t)z * C_ + m) * C_ + n) =
                        __floats2half2_rn(v0, v1);
                } else if (EPI == EPI_CTX) {
                    const int r = n >> 6, d = n & 63;
                    *(__half2*)(CoutH + ((size_t)(r * C_) + m) * E_ + z * D_ + d) =
                        __floats2half2_rn(v0, v1);
                } else { // EPI_OPROJ
                    float2* dst = (float2*)(CoutF + (size_t)m * E_ + n);
                    *dst = make_float2(v0 + biasQ[n], v1 + biasQ[n + 1]);
                }
            }
        }
    }
}

// ---------------------------------------------------------------------------
// Masked softmax; sums KSPLIT fp16 partials in fp32. fp32 to d_out, fp16 to P.
// Block 0 also copies the l passthrough.
// ---------------------------------------------------------------------------
__global__ void __launch_bounds__(512)
softmax_kernel(const __half* __restrict__ Sp, __half* __restrict__ P,
               float* __restrict__ Pout,
               const float* __restrict__ l, float* __restrict__ lOut)
{
    const int row = blockIdx.x;
    const int h   = row >> 9;
    const int i   = row & (C_ - 1);
    const int j   = threadIdx.x;
    const int lane = j & 31, warp = j >> 5;
    __shared__ float red[16];

    if (row == 0 && j < H_) lOut[j] = l[j];

    const __half* base = Sp + (((size_t)h * KSPLIT) * C_ + i) * C_ + j;
    float x = __half2float(base[0]);
#pragma unroll
    for (int kh = 1; kh < KSPLIT; kh++)
        x += __half2float(base[(size_t)kh * C_ * C_]);
    if (j == i) x = -1e9f;

    float m = x;
#pragma unroll
    for (int o = 16; o > 0; o >>= 1) m = fmaxf(m, __shfl_xor_sync(~0u, m, o));
    if (lane == 0) red[warp] = m;
    __syncthreads();
    if (j < 16) {
        float t = red[j];
#pragma unroll
        for (int o = 8; o > 0; o >>= 1) t = fmaxf(t, __shfl_xor_sync(0xffffu, t, o));
        if (j == 0) red[0] = t;
    }
    __syncthreads();
    const float mx = red[0];
    __syncthreads();

    float e = __expf(x - mx);
    float sacc = e;
#pragma unroll
    for (int o = 16; o > 0; o >>= 1) sacc += __shfl_xor_sync(~0u, sacc, o);
    if (lane == 0) red[warp] = sacc;
    __syncthreads();
    if (j < 16) {
        float t = red[j];
#pragma unroll
        for (int o = 8; o > 0; o >>= 1) t += __shfl_xor_sync(0xffffu, t, o);
        if (j == 0) red[0] = t;
    }
    __syncthreads();
    const float inv = 1.0f / red[0];

    const float p = e * inv;
    const size_t idx = (size_t)row * C_ + j;
    P[idx]    = __float2half_rn(p);
    Pout[idx] = p;
}

// ---------------------------------------------------------------------------
// Launch
// ---------------------------------------------------------------------------
extern "C" void kernel_launch(void* const* d_in, const int* in_sizes, int n_in,
                              void* d_out, int out_size)
{
    const float* x  = (const float*)d_in[0];
    const float* Wq = (const float*)d_in[2];
    const float* bq = (const float*)d_in[3];
    const float* Wk = (const float*)d_in[4];
    const float* bk = (const float*)d_in[5];
    const float* Wv = (const float*)d_in[6];
    const float* bv = (const float*)d_in[7];
    const float* Wo = (const float*)d_in[8];
    const float* bo = (const float*)d_in[9];
    const float* l  = (const float*)d_in[10];
    float* out = (float*)d_out;

    __half *pXh, *pWh, *pQ, *pK, *pVt, *pSp, *pP, *pCtx;
    cudaGetSymbolAddress((void**)&pXh,  g_xh);
    cudaGetSymbolAddress((void**)&pWh,  g_Wh);
    cudaGetSymbolAddress((void**)&pQ,   g_Q);
    cudaGetSymbolAddress((void**)&pK,   g_K);
    cudaGetSymbolAddress((void**)&pVt,  g_Vt);
    cudaGetSymbolAddress((void**)&pSp,  g_Sp);
    cudaGetSymbolAddress((void**)&pP,   g_P);
    cudaGetSymbolAddress((void**)&pCtx, g_ctx);

    cudaFuncSetAttribute(mm_kernel<EPI_PROJ>,   cudaFuncAttributeMaxDynamicSharedMemorySize, SMEM_BYTES);
    cudaFuncSetAttribute(mm_kernel<EPI_LOGITS>, cudaFuncAttributeMaxDynamicSharedMemorySize, SMEM_BYTES);
    cudaFuncSetAttribute(mm_kernel<EPI_CTX>,    cudaFuncAttributeMaxDynamicSharedMemorySize, SMEM_BYTES);
    cudaFuncSetAttribute(mm_kernel<EPI_OPROJ>,  cudaFuncAttributeMaxDynamicSharedMemorySize, SMEM_BYTES);

    const size_t WSZ = (size_t)E_ * E_;

    // 0) fp16 conversion: x on legacy stream, W's on the side stream.
    {
        cudaEventRecord(g_aux.evFork, 0);
        cudaStreamWaitEvent(g_aux.sB, g_aux.evFork, 0);
        int n4w = (int)(WSZ / 4);
        dim3 gW((n4w + 255) / 256, 4);
        f2h_w_kernel<<<gW, 256, 0, g_aux.sB>>>(Wq, Wk, Wv, Wo, pWh, n4w);
        cudaEventRecord(g_aux.evJoin, g_aux.sB);

        int n4x = (int)((size_t)M_TOK * E_ / 4);
        f2h_kernel<<<(n4x + 255) / 256, 256>>>(x, pXh, n4x);

        cudaStreamWaitEvent(0, g_aux.evJoin, 0);
    }

    const dim3 gProj (E_ / BN, M_TOK / BM, 3);          // 12 x 256 x 3
    const dim3 gLog  (C_ / BN, C_ / BM, H_ * KSPLIT);   // 8 x 4 x 48
    const dim3 gCtx  (RD / BN, C_ / BM, H_);            // 64 x 4 x 12
    const dim3 gOut  (E_ / BN, M_TOK / BM, 1);          // 12 x 256

    // 1) fused Q/K/V projections
    mm_kernel<EPI_PROJ><<<gProj, 256, SMEM_BYTES>>>(
        pXh, pWh, bq, bk, bv, pQ, pK, pVt, nullptr, nullptr, E_, E_, E_);

    // 2) tied-row logits, split-K x4, fp16 partials
    mm_kernel<EPI_LOGITS><<<gLog, 256, SMEM_BYTES>>>(
        pQ, pK, nullptr, nullptr, nullptr, nullptr, nullptr, nullptr,
        nullptr, pSp, HRD, HRD, KPART);

    // 3) masked softmax (+ fused l passthrough)
    softmax_kernel<<<H_ * C_, 512>>>(pSp, pP, out + OUT_OFF_P,
                                     l, out + OUT_OFF_L);

    // 4) context
    mm_kernel<EPI_CTX><<<gCtx, 256, SMEM_BYTES>>>(
        pP, pVt, nullptr, nullptr, nullptr, nullptr, nullptr, nullptr,
        nullptr, pCtx, C_, C_, C_);

    // 5) output projection
    mm_kernel<EPI_OPROJ><<<gOut, 256, SMEM_BYTES>>>(
        pCtx, pWh + 3 * WSZ, bo, nullptr, nullptr, nullptr, nullptr, nullptr,
        out, nullptr, E_, E_, E_);
}

// round 17
// speedup vs baseline: 1.0053x; 1.0035x over previous
#include <cuda_runtime.h>
#include <cuda_fp16.h>
#include <cstdint>

// ---------------------------------------------------------------------------
// Problem constants
// ---------------------------------------------------------------------------
constexpr int R_ = 64, C_ = 512, H_ = 12, D_ = 64, E_ = 768;
constexpr int M_TOK = R_ * C_;   // 32768
constexpr int RD    = R_ * D_;   // 4096
constexpr int HRD   = H_ * RD;   // 49152
constexpr long OUT_OFF_P = (long)M_TOK * E_;
constexpr long OUT_OFF_L = OUT_OFF_P + (long)H_ * C_ * C_;
constexpr float SCALING = 0.015625f;  // D^-0.5 / sqrt(R)
constexpr int KSPLIT = 4;
constexpr int KPART  = RD / KSPLIT;   // 1024

// ---------------------------------------------------------------------------
// Scratch
// ---------------------------------------------------------------------------
__device__ __half g_xh [(size_t)M_TOK * E_];
__device__ __half g_Wh [4 * (size_t)E_ * E_];
__device__ __half g_Q  [(size_t)C_ * HRD];          // [i][h][r][d]
__device__ __half g_K  [(size_t)C_ * HRD];          // [i][h][r][d]
__device__ __half g_Vt [(size_t)H_ * RD * C_];      // [h][r*D+d][i]
__device__ __half g_Sp [(size_t)H_ * KSPLIT * C_ * C_];  // fp16 logit partials
__device__ __half g_P  [(size_t)H_ * C_ * C_];
__device__ __half g_ctx[(size_t)M_TOK * E_];

// ---------------------------------------------------------------------------
// Helpers
// ---------------------------------------------------------------------------
__device__ __forceinline__ uint32_t smem_u32(const void* p) {
    uint32_t a;
    asm("{ .reg .u64 t; cvta.to.shared.u64 t, %1; cvt.u32.u64 %0, t; }"
        : "=r"(a) : "l"(p));
    return a;
}
__device__ __forceinline__ void cpa16(uint32_t dst, const void* src) {
    asm volatile("cp.async.cg.shared.global [%0], [%1], 16;"
                 :: "r"(dst), "l"(src) : "memory");
}
__device__ __forceinline__ void ldsm4(uint32_t& r0, uint32_t& r1,
                                      uint32_t& r2, uint32_t& r3, uint32_t addr) {
    asm volatile("ldmatrix.sync.aligned.m8n8.x4.shared.b16 {%0,%1,%2,%3}, [%4];"
                 : "=r"(r0), "=r"(r1), "=r"(r2), "=r"(r3) : "r"(addr));
}

// ---------------------------------------------------------------------------
// Single fused f32->f16 conversion pass: x (6144 blocks) + 4 W's (2304 blocks)
// in one launch via flattened block index.
// ---------------------------------------------------------------------------
constexpr int N4_X = (int)((size_t)M_TOK * E_ / 4);   // 6,291,456/4 = 1,572,864
constexpr int N4_W = (int)((size_t)E_ * E_ / 4);      // 147,456
constexpr int BLK_X = (N4_X + 255) / 256;             // 6144
constexpr int BLK_W = (N4_W + 255) / 256;             // 576

__global__ void __launch_bounds__(256)
f2h_all_kernel(const float* __restrict__ x,
               const float* __restrict__ w0, const float* __restrict__ w1,
               const float* __restrict__ w2, const float* __restrict__ w3,
               __half* __restrict__ xh, __half* __restrict__ wh)
{
    const int b = blockIdx.x;
    const float* src;
    __half* dst;
    int i;
    if (b < BLK_X) {
        i = b * 256 + threadIdx.x;
        if (i >= N4_X) return;
        src = x; dst = xh;
    } else {
        const int wb = b - BLK_X;
        const int w = wb / BLK_W;               // 0..3
        i = (wb - w * BLK_W) * 256 + threadIdx.x;
        if (i >= N4_W) return;
        src = (w == 0) ? w0 : (w == 1) ? w1 : (w == 2) ? w2 : w3;
        dst = wh + (size_t)w * E_ * E_;
    }
    float4 v = ((const float4*)src)[i];
    __half2* o = (__half2*)(dst + (size_t)i * 4);
    o[0] = __floats2half2_rn(v.x, v.y);
    o[1] = __floats2half2_rn(v.z, v.w);
}

// ---------------------------------------------------------------------------
// fp16 mma.sync GEMM, fp32 accumulate. Block 128x64x64, 8 warps (4m x 2n),
// warp tile 32x32. 2-stage cp.async pipeline, BK=64. 3 CTAs/SM (24 warps).
// Pipeline ordering: wait -> barrier -> issue next load -> compute. (verified)
// ---------------------------------------------------------------------------
constexpr int BM = 128, BN = 64, BK = 64;
constexpr int STAGES = 2;
constexpr int AS_STRIDE = 72;                     // halves per row (144 B)
constexpr int BS_STRIDE = 72;
constexpr int AS_HALVES = BM * AS_STRIDE;         // 9216
constexpr int BS_HALVES = BN * BS_STRIDE;         // 4608
constexpr int STAGE_HALVES = AS_HALVES + BS_HALVES;   // 13824 (27648 B)
constexpr int SMEM_BYTES = STAGES * STAGE_HALVES * 2; // 55296

enum { EPI_PROJ = 0, EPI_LOGITS = 2, EPI_CTX = 3, EPI_OPROJ = 4 };

template <int EPI>
__global__ void __launch_bounds__(256, 3)
mm_kernel(const __half* __restrict__ A, const __half* __restrict__ Bw,
          const float* __restrict__ biasQ, const float* __restrict__ biasK,
          const float* __restrict__ biasV,
          __half* __restrict__ dQ, __half* __restrict__ dK, __half* __restrict__ dVt,
          float* __restrict__ CoutF, __half* __restrict__ CoutH,
          int lda, int ldb, int K)
{
    extern __shared__ __half sm[];
    const int tid = threadIdx.x;
    const int wid = tid >> 5, lane = tid & 31;
    const int m0 = blockIdx.y * BM;
    const int n0 = blockIdx.x * BN;
    const int z  = blockIdx.z;

    const __half* B = Bw;
    if (EPI == EPI_PROJ)   { B  = Bw + (size_t)z * E_ * E_; }
    if (EPI == EPI_LOGITS) {
        const int head = z >> 2, kh = z & 3;     // z = head*KSPLIT + kpart
        A += (size_t)head * RD + (size_t)kh * KPART;
        B  = Bw + (size_t)head * RD + (size_t)kh * KPART;
    }
    if (EPI == EPI_CTX)    { A += (size_t)z * C_ * C_; B = Bw + (size_t)z * RD * C_; }

    const uint32_t smb = smem_u32(sm);

    const int warp_m = wid >> 1;          // 0..3 -> 32-row slices
    const int warp_n = wid & 1;           // 0..1 -> 32-col slices
    const int mb_base = warp_m * 32;
    const int nb_base = warp_n * 32;
    const int r4 = lane >> 2, c4 = lane & 3;

    const uint32_t a_off =
        (uint32_t)(((mb_base + (lane & 15)) * AS_STRIDE + ((lane >> 4) * 8)) * 2);
    const uint32_t b_off =
        (uint32_t)(((nb_base + (lane & 7) + ((lane & 16) >> 1)) * BS_STRIDE +
                    (((lane >> 3) & 1) * 8)) * 2);

    float acc[2][4][4];
#pragma unroll
    for (int a = 0; a < 2; a++)
#pragma unroll
        for (int b = 0; b < 4; b++)
#pragma unroll
            for (int c = 0; c < 4; c++) acc[a][b][c] = 0.f;

    const int NC = K / BK;

    auto load_stage = [&](int c, int s) {
        const __half* Ab = A + (size_t)m0 * lda + c * BK;
        const __half* Bb = B + (size_t)n0 * ldb + c * BK;
        const uint32_t asb = smb + (uint32_t)(s * STAGE_HALVES) * 2u;
        const uint32_t bsb = asb + AS_HALVES * 2u;
#pragma unroll
        for (int i = 0; i < 4; i++) {          // A: 128 rows x 8 f8 = 1024 cp
            int q = i * 256 + tid;
            int row = q >> 3, kq = q & 7;
            cpa16(asb + (uint32_t)(row * AS_STRIDE + kq * 8) * 2u,
                  Ab + (size_t)row * lda + kq * 8);
        }
#pragma unroll
        for (int i = 0; i < 2; i++) {          // B: 64 rows x 8 f8 = 512 cp
            int q = i * 256 + tid;
            int row = q >> 3, kq = q & 7;
            cpa16(bsb + (uint32_t)(row * BS_STRIDE + kq * 8) * 2u,
                  Bb + (size_t)row * ldb + kq * 8);
        }
        asm volatile("cp.async.commit_group;" ::: "memory");
    };

    load_stage(0, 0);

    int sidx = 0;
    for (int c = 0; c < NC; c++) {
        // wait for ALL outstanding loads (including load(c)), then barrier:
        // publishes load(c) to every warp AND guarantees no warp still reads
        // buffer sidx^1 (iteration c-1) before we overwrite it below.
        asm volatile("cp.async.wait_group 0;" ::: "memory");
        __syncthreads();

        if (c + 1 < NC) load_stage(c + 1, sidx ^ 1);   // overlaps compute below

        const uint32_t abase = smb + (uint32_t)(sidx * STAGE_HALVES) * 2u + a_off;
        const uint32_t bbase = smb + (uint32_t)(sidx * STAGE_HALVES + AS_HALVES) * 2u + b_off;

#pragma unroll
        for (int s = 0; s < 4; s++) {          // 4 substeps of k16
            const int ks = s * 16;
            uint32_t afr[2][4], bfr[4][2];
#pragma unroll
            for (int mb = 0; mb < 2; mb++)
                ldsm4(afr[mb][0], afr[mb][1], afr[mb][2], afr[mb][3],
                      abase + (uint32_t)((mb * 16 * AS_STRIDE + ks) * 2));
#pragma unroll
            for (int p = 0; p < 2; p++)
                ldsm4(bfr[2*p][0], bfr[2*p][1], bfr[2*p+1][0], bfr[2*p+1][1],
                      bbase + (uint32_t)((p * 16 * BS_STRIDE + ks) * 2));
#pragma unroll
            for (int mb = 0; mb < 2; mb++)
#pragma unroll
                for (int nb = 0; nb < 4; nb++) {
                    asm volatile(
                        "mma.sync.aligned.m16n8k16.row.col.f32.f16.f16.f32 "
                        "{%0,%1,%2,%3}, {%4,%5,%6,%7}, {%8,%9}, {%0,%1,%2,%3};"
                        : "+f"(acc[mb][nb][0]), "+f"(acc[mb][nb][1]),
                          "+f"(acc[mb][nb][2]), "+f"(acc[mb][nb][3])
                        : "r"(afr[mb][0]), "r"(afr[mb][1]),
                          "r"(afr[mb][2]), "r"(afr[mb][3]),
                          "r"(bfr[nb][0]), "r"(bfr[nb][1]));
                }
        }
        sidx ^= 1;
    }

    // ---- epilogue
#pragma unroll
    for (int mb = 0; mb < 2; mb++) {
#pragma unroll
        for (int half_ = 0; half_ < 2; half_++) {
            const int m = m0 + mb_base + mb * 16 + r4 + half_ * 8;
#pragma unroll
            for (int nb = 0; nb < 4; nb++) {
                const int n = n0 + nb_base + nb * 8 + c4 * 2;
                float v0 = acc[mb][nb][half_ * 2 + 0];
                float v1 = acc[mb][nb][half_ * 2 + 1];

                if (EPI == EPI_PROJ) {
                    const int r = m >> 9, ic = m & 511;
                    const int h = n >> 6, d = n & 63;
                    if (z == 0) {
                        v0 = (v0 + biasQ[n])     * SCALING;
                        v1 = (v1 + biasQ[n + 1]) * SCALING;
                        *(__half2*)(dQ + (((size_t)ic * H_ + h) * R_ + r) * D_ + d) =
                            __floats2half2_rn(v0, v1);
                    } else if (z == 1) {
                        v0 += biasK[n]; v1 += biasK[n + 1];
                        *(__half2*)(dK + (((size_t)ic * H_ + h) * R_ + r) * D_ + d) =
                            __floats2half2_rn(v0, v1);
                    } else {
                        v0 += biasV[n]; v1 += biasV[n + 1];
                        __half* dst = dVt + ((size_t)h * RD + r * D_ + d) * C_ + ic;
                        dst[0]  = __float2half_rn(v0);
                        dst[C_] = __float2half_rn(v1);
                    }
                } else if (EPI == EPI_LOGITS) {
                    // fp16 partials halve softmax-side traffic
                    *(__half2*)(CoutH + ((size_t)z * C_ + m) * C_ + n) =
                        __floats2half2_rn(v0, v1);
                } else if (EPI == EPI_CTX) {
                    const int r = n >> 6, d = n & 63;
                    *(__half2*)(CoutH + ((size_t)(r * C_) + m) * E_ + z * D_ + d) =
                        __floats2half2_rn(v0, v1);
                } else { // EPI_OPROJ
                    float2* dst = (float2*)(CoutF + (size_t)m * E_ + n);
                    *dst = make_float2(v0 + biasQ[n], v1 + biasQ[n + 1]);
                }
            }
        }
    }
}

// ---------------------------------------------------------------------------
// Masked softmax; sums KSPLIT fp16 partials in fp32. fp32 to d_out, fp16 to P.
// Block 0 also copies the l passthrough.
// ---------------------------------------------------------------------------
__global__ void __launch_bounds__(512)
softmax_kernel(const __half* __restrict__ Sp, __half* __restrict__ P,
               float* __restrict__ Pout,
               const float* __restrict__ l, float* __restrict__ lOut)
{
    const int row = blockIdx.x;
    const int h   = row >> 9;
    const int i   = row & (C_ - 1);
    const int j   = threadIdx.x;
    const int lane = j & 31, warp = j >> 5;
    __shared__ float red[16];

    if (row == 0 && j < H_) lOut[j] = l[j];

    const __half* base = Sp + (((size_t)h * KSPLIT) * C_ + i) * C_ + j;
    float x = __half2float(base[0]);
#pragma unroll
    for (int kh = 1; kh < KSPLIT; kh++)
        x += __half2float(base[(size_t)kh * C_ * C_]);
    if (j == i) x = -1e9f;

    float m = x;
#pragma unroll
    for (int o = 16; o > 0; o >>= 1) m = fmaxf(m, __shfl_xor_sync(~0u, m, o));
    if (lane == 0) red[warp] = m;
    __syncthreads();
    if (j < 16) {
        float t = red[j];
#pragma unroll
        for (int o = 8; o > 0; o >>= 1) t = fmaxf(t, __shfl_xor_sync(0xffffu, t, o));
        if (j == 0) red[0] = t;
    }
    __syncthreads();
    const float mx = red[0];
    __syncthreads();

    float e = __expf(x - mx);
    float sacc = e;
#pragma unroll
    for (int o = 16; o > 0; o >>= 1) sacc += __shfl_xor_sync(~0u, sacc, o);
    if (lane == 0) red[warp] = sacc;
    __syncthreads();
    if (j < 16) {
        float t = red[j];
#pragma unroll
        for (int o = 8; o > 0; o >>= 1) t += __shfl_xor_sync(0xffffu, t, o);
        if (j == 0) red[0] = t;
    }
    __syncthreads();
    const float inv = 1.0f / red[0];

    const float p = e * inv;
    const size_t idx = (size_t)row * C_ + j;
    P[idx]    = __float2half_rn(p);
    Pout[idx] = p;
}

// ---------------------------------------------------------------------------
// Launch
// ---------------------------------------------------------------------------
extern "C" void kernel_launch(void* const* d_in, const int* in_sizes, int n_in,
                              void* d_out, int out_size)
{
    const float* x  = (const float*)d_in[0];
    const float* Wq = (const float*)d_in[2];
    const float* bq = (const float*)d_in[3];
    const float* Wk = (const float*)d_in[4];
    const float* bk = (const float*)d_in[5];
    const float* Wv = (const float*)d_in[6];
    const float* bv = (const float*)d_in[7];
    const float* Wo = (const float*)d_in[8];
    const float* bo = (const float*)d_in[9];
    const float* l  = (const float*)d_in[10];
    float* out = (float*)d_out;

    __half *pXh, *pWh, *pQ, *pK, *pVt, *pSp, *pP, *pCtx;
    cudaGetSymbolAddress((void**)&pXh,  g_xh);
    cudaGetSymbolAddress((void**)&pWh,  g_Wh);
    cudaGetSymbolAddress((void**)&pQ,   g_Q);
    cudaGetSymbolAddress((void**)&pK,   g_K);
    cudaGetSymbolAddress((void**)&pVt,  g_Vt);
    cudaGetSymbolAddress((void**)&pSp,  g_Sp);
    cudaGetSymbolAddress((void**)&pP,   g_P);
    cudaGetSymbolAddress((void**)&pCtx, g_ctx);

    cudaFuncSetAttribute(mm_kernel<EPI_PROJ>,   cudaFuncAttributeMaxDynamicSharedMemorySize, SMEM_BYTES);
    cudaFuncSetAttribute(mm_kernel<EPI_LOGITS>, cudaFuncAttributeMaxDynamicSharedMemorySize, SMEM_BYTES);
    cudaFuncSetAttribute(mm_kernel<EPI_CTX>,    cudaFuncAttributeMaxDynamicSharedMemorySize, SMEM_BYTES);
    cudaFuncSetAttribute(mm_kernel<EPI_OPROJ>,  cudaFuncAttributeMaxDynamicSharedMemorySize, SMEM_BYTES);

    const size_t WSZ = (size_t)E_ * E_;

    // 0) single fused fp16 conversion (x + all 4 W's, one launch)
    f2h_all_kernel<<<BLK_X + 4 * BLK_W, 256>>>(x, Wq, Wk, Wv, Wo, pXh, pWh);

    const dim3 gProj (E_ / BN, M_TOK / BM, 3);          // 12 x 256 x 3
    const dim3 gLog  (C_ / BN, C_ / BM, H_ * KSPLIT);   // 8 x 4 x 48
    const dim3 gCtx  (RD / BN, C_ / BM, H_);            // 64 x 4 x 12
    const dim3 gOut  (E_ / BN, M_TOK / BM, 1);          // 12 x 256

    // 1) fused Q/K/V projections
    mm_kernel<EPI_PROJ><<<gProj, 256, SMEM_BYTES>>>(
        pXh, pWh, bq, bk, bv, pQ, pK, pVt, nullptr, nullptr, E_, E_, E_);

    // 2) tied-row logits, split-K x4, fp16 partials
    mm_kernel<EPI_LOGITS><<<gLog, 256, SMEM_BYTES>>>(
        pQ, pK, nullptr, nullptr, nullptr, nullptr, nullptr, nullptr,
        nullptr, pSp, HRD, HRD, KPART);

    // 3) masked softmax (+ fused l passthrough)
    softmax_kernel<<<H_ * C_, 512>>>(pSp, pP, out + OUT_OFF_P,
                                     l, out + OUT_OFF_L);

    // 4) context
    mm_kernel<EPI_CTX><<<gCtx, 256, SMEM_BYTES>>>(
        pP, pVt, nullptr, nullptr, nullptr, nullptr, nullptr, nullptr,
        nullptr, pCtx, C_, C_, C_);

    // 5) output projection
    mm_kernel<EPI_OPROJ><<<gOut, 256, SMEM_BYTES>>>(
        pCtx, pWh + 3 * WSZ, bo, nullptr, nullptr, nullptr, nullptr, nullptr,
        out, nullptr, E_, E_, E_);
}